// round 2
// baseline (speedup 1.0000x reference)
#include <cuda_runtime.h>
#include <math.h>

#define SEQ_C 1024
#define HD_C 64
#define NH_C 64
#define SCALE_C 0.125f

// 256 MB scratch for P[n, i, t] = Qv[n,i] . R[h,t]
__device__ float g_pos[(size_t)NH_C * SEQ_C * SEQ_C];

// ---------------------------------------------------------------------------
// Kernel 1: pos GEMM, BM=BN=128, K=64, 256 threads, 8x8 micro-tile.
// ---------------------------------------------------------------------------
__global__ __launch_bounds__(256)
void pos_gemm_kernel(const float* __restrict__ q,
                     const float* __restrict__ vbias,
                     const float* __restrict__ R)
{
    __shared__ float Qs[64 * 132];   // [d][i] transposed (pad 132)
    __shared__ float Rs[64 * 132];   // [d][t] transposed

    const int tid = threadIdx.x;
    const int n  = blockIdx.z;
    const int h  = n & 15;
    const int i0 = blockIdx.y << 7;
    const int t0 = blockIdx.x << 7;

    const float* qb = q + (size_t)n * 65536 + (size_t)i0 * 64;
    const float* rb = R + (size_t)h * (2048 * 64) + (size_t)t0 * 64;

    #pragma unroll
    for (int it = 0; it < 32; ++it) {
        int idx = it * 256 + tid;
        int r = idx >> 6, c = idx & 63;
        Qs[c * 132 + r] = qb[idx] * SCALE_C + vbias[h * 64 + c];
        Rs[c * 132 + r] = rb[idx];
    }
    __syncthreads();

    const int ty = tid >> 4, tx = tid & 15;
    float acc[8][8] = {};

    #pragma unroll 4
    for (int kd = 0; kd < 64; ++kd) {
        float a[8], b[8];
        *(float4*)&a[0] = *(const float4*)(Qs + kd * 132 + ty * 8);
        *(float4*)&a[4] = *(const float4*)(Qs + kd * 132 + ty * 8 + 4);
        *(float4*)&b[0] = *(const float4*)(Rs + kd * 132 + tx * 8);
        *(float4*)&b[4] = *(const float4*)(Rs + kd * 132 + tx * 8 + 4);
        #pragma unroll
        for (int ii = 0; ii < 8; ++ii)
            #pragma unroll
            for (int jj = 0; jj < 8; ++jj)
                acc[ii][jj] += a[ii] * b[jj];
    }

    float* ob = g_pos + ((size_t)n << 20) + ((size_t)(i0 + ty * 8) << 10) + t0 + tx * 8;
    #pragma unroll
    for (int ii = 0; ii < 8; ++ii) {
        *(float4*)(ob + ((size_t)ii << 10))     = make_float4(acc[ii][0], acc[ii][1], acc[ii][2], acc[ii][3]);
        *(float4*)(ob + ((size_t)ii << 10) + 4) = make_float4(acc[ii][4], acc[ii][5], acc[ii][6], acc[ii][7]);
    }
}

// ---------------------------------------------------------------------------
// Kernel 2: flash attention, BM=128 (i), BN=128 (j), 256 threads, 8x8 tiles.
//   score[i,j] = (q[i]*scale + u_bias).K[j] + shift(P)[i,j]
//   shift(P)[i,j] = P[i, 1023+j-i] (j<=i) ; 0 (j==i+1) ; P[i+1, j-i-2] (j>=i+2)
// ---------------------------------------------------------------------------
__global__ __launch_bounds__(256)
void flash_kernel(const float* __restrict__ q,
                  const float* __restrict__ k,
                  const float* __restrict__ v,
                  const float* __restrict__ ubias,
                  float* __restrict__ out)
{
    extern __shared__ float sm[];
    float* Qus = sm;                    // [64][132] d-major
    float* Ks  = sm + 64 * 132;         // [64][132] d-major
    float* Ps  = sm + 2 * 64 * 132;     // [128][132] i-major probs
    float* Vs  = sm + 2 * 64 * 132 + 128 * 132;  // [128][64] natural

    const int tid = threadIdx.x;
    const int ty = tid >> 4, tx = tid & 15;
    const int n  = blockIdx.y;
    const int h  = n & 15;
    const int i0 = blockIdx.x << 7;

    const float* qb = q + (size_t)n * 65536 + (size_t)i0 * 64;
    #pragma unroll
    for (int it = 0; it < 32; ++it) {
        int idx = it * 256 + tid;
        int r = idx >> 6, c = idx & 63;
        Qus[c * 132 + r] = qb[idx] * SCALE_C + ubias[h * 64 + c];
    }

    float m[8], l[8], O[8][4];
    #pragma unroll
    for (int ii = 0; ii < 8; ++ii) {
        m[ii] = -1e30f; l[ii] = 0.0f;
        #pragma unroll
        for (int dd = 0; dd < 4; ++dd) O[ii][dd] = 0.0f;
    }

    const float* posb = g_pos + ((size_t)n << 20);
    const float* kb0  = k + (size_t)n * 65536;
    const float* vb0  = v + (size_t)n * 65536;

    for (int kt = 0; kt < 8; ++kt) {
        const int j0 = kt << 7;
        __syncthreads();   // previous PV done with Ks/Vs/Ps

        const float* kb = kb0 + (size_t)j0 * 64;
        const float* vb = vb0 + (size_t)j0 * 64;
        #pragma unroll
        for (int it = 0; it < 32; ++it) {
            int idx = it * 256 + tid;
            int r = idx >> 6, c = idx & 63;
            Ks[c * 132 + r] = kb[idx];
            Vs[idx] = vb[idx];
        }
        __syncthreads();

        // ---- content scores: 8x8 micro-GEMM ----
        float acc[8][8] = {};
        #pragma unroll 4
        for (int kd = 0; kd < 64; ++kd) {
            float a[8], b[8];
            *(float4*)&a[0] = *(const float4*)(Qus + kd * 132 + ty * 8);
            *(float4*)&a[4] = *(const float4*)(Qus + kd * 132 + ty * 8 + 4);
            *(float4*)&b[0] = *(const float4*)(Ks  + kd * 132 + tx * 8);
            *(float4*)&b[4] = *(const float4*)(Ks  + kd * 132 + tx * 8 + 4);
            #pragma unroll
            for (int ii = 0; ii < 8; ++ii)
                #pragma unroll
                for (int jj = 0; jj < 8; ++jj)
                    acc[ii][jj] += a[ii] * b[jj];
        }

        // ---- add shifted positional scores ----
        #pragma unroll
        for (int ii = 0; ii < 8; ++ii) {
            const int i = i0 + ty * 8 + ii;
            #pragma unroll
            for (int jj = 0; jj < 8; ++jj) {
                const int j = j0 + tx * 8 + jj;
                float p;
                if (j <= i)          p = posb[((size_t)i << 10) + (size_t)(1023 - i + j)];
                else if (j == i + 1) p = 0.0f;
                else                 p = posb[((size_t)(i + 1) << 10) + (size_t)(j - i - 2)];
                acc[ii][jj] += p;
            }
        }

        // ---- online softmax (16-lane row reductions) ----
        #pragma unroll
        for (int ii = 0; ii < 8; ++ii) {
            float tm = acc[ii][0];
            #pragma unroll
            for (int jj = 1; jj < 8; ++jj) tm = fmaxf(tm, acc[ii][jj]);
            #pragma unroll
            for (int off = 1; off < 16; off <<= 1)
                tm = fmaxf(tm, __shfl_xor_sync(0xffffffffu, tm, off));
            float mn = fmaxf(m[ii], tm);
            float corr = __expf(m[ii] - mn);
            m[ii] = mn;
            float rs = 0.0f;
            #pragma unroll
            for (int jj = 0; jj < 8; ++jj) {
                acc[ii][jj] = __expf(acc[ii][jj] - mn);
                rs += acc[ii][jj];
            }
            #pragma unroll
            for (int off = 1; off < 16; off <<= 1)
                rs += __shfl_xor_sync(0xffffffffu, rs, off);
            l[ii] = l[ii] * corr + rs;
            #pragma unroll
            for (int dd = 0; dd < 4; ++dd) O[ii][dd] *= corr;
        }

        // ---- stage probs (i-major) ----
        #pragma unroll
        for (int ii = 0; ii < 8; ++ii) {
            *(float4*)(Ps + (ty * 8 + ii) * 132 + tx * 8)     = make_float4(acc[ii][0], acc[ii][1], acc[ii][2], acc[ii][3]);
            *(float4*)(Ps + (ty * 8 + ii) * 132 + tx * 8 + 4) = make_float4(acc[ii][4], acc[ii][5], acc[ii][6], acc[ii][7]);
        }
        __syncthreads();

        // ---- O += probs @ V  (P float4 along j, V float4 along d) ----
        #pragma unroll 2
        for (int j = 0; j < 128; j += 4) {
            float4 v0 = *(const float4*)(Vs + (j + 0) * 64 + tx * 4);
            float4 v1 = *(const float4*)(Vs + (j + 1) * 64 + tx * 4);
            float4 v2 = *(const float4*)(Vs + (j + 2) * 64 + tx * 4);
            float4 v3 = *(const float4*)(Vs + (j + 3) * 64 + tx * 4);
            #pragma unroll
            for (int ii = 0; ii < 8; ++ii) {
                float4 p = *(const float4*)(Ps + (ty * 8 + ii) * 132 + j);
                O[ii][0] += p.x * v0.x + p.y * v1.x + p.z * v2.x + p.w * v3.x;
                O[ii][1] += p.x * v0.y + p.y * v1.y + p.z * v2.y + p.w * v3.y;
                O[ii][2] += p.x * v0.z + p.y * v1.z + p.z * v2.z + p.w * v3.z;
                O[ii][3] += p.x * v0.w + p.y * v1.w + p.z * v2.w + p.w * v3.w;
            }
        }
    }

    float* ob = out + (size_t)n * 65536 + (size_t)(i0 + ty * 8) * 64 + tx * 4;
    #pragma unroll
    for (int ii = 0; ii < 8; ++ii) {
        float inv = 1.0f / l[ii];
        *(float4*)(ob + ii * 64) =
            make_float4(O[ii][0] * inv, O[ii][1] * inv, O[ii][2] * inv, O[ii][3] * inv);
    }
}

// ---------------------------------------------------------------------------
extern "C" void kernel_launch(void* const* d_in, const int* in_sizes, int n_in,
                              void* d_out, int out_size)
{
    const float* q  = (const float*)d_in[0];
    const float* k  = (const float*)d_in[1];
    const float* v  = (const float*)d_in[2];
    const float* ub = (const float*)d_in[3];
    const float* vb = (const float*)d_in[4];
    const float* R  = (const float*)d_in[5];
    float* out = (float*)d_out;

    const int SMEM2 = (2 * 64 * 132 + 128 * 132 + 128 * 64) * (int)sizeof(float); // 167936 B
    cudaFuncSetAttribute(flash_kernel, cudaFuncAttributeMaxDynamicSharedMemorySize, SMEM2);

    pos_gemm_kernel<<<dim3(8, 8, 64), 256>>>(q, vb, R);
    flash_kernel<<<dim3(8, 64), 256, SMEM2>>>(q, k, v, ub, out);
}